// round 1
// baseline (speedup 1.0000x reference)
#include <cuda_runtime.h>

#define BSZ 8
#define HID 64
#define NV  1024
#define NT  64
#define TW  64
#define KC  64
#define PAD 68   // row stride in shared: 16B-aligned float4 rows, bank-spread

// Ping-pong recurrent state, layout [buf][b][v][hid] (v-major so GEMM loads coalesce)
__device__ float g_h[2][BSZ][NV][HID];
__device__ int   g_mask_mode;   // 0 = byte/bool, 1 = int32, 2 = float32

// ---------------------------------------------------------------------------
// Mask dtype detection: scan first quarter of the buffer (safe under every
// candidate layout) as u32 words. int32 layout => every word in {0,1}.
// float32 layout => every word in {0, 0x3F800000}. Otherwise bytes.
// All-zero mask is layout-ambiguous but semantically identical either way.
// ---------------------------------------------------------------------------
__global__ void detect_mask_kernel(const unsigned int* __restrict__ m) {
    __shared__ int viol_i, viol_f;
    if (threadIdx.x == 0) { viol_i = 0; viol_f = 0; }
    __syncthreads();
    int li = 0, lf = 0;
    const int nwords = (BSZ * NV * NT) / 4;
    for (int i = threadIdx.x; i < nwords; i += blockDim.x) {
        unsigned int w = m[i];
        if (w > 1u) li = 1;
        if (w != 0u && w != 0x3F800000u) lf = 1;
    }
    if (li) atomicOr(&viol_i, 1);
    if (lf) atomicOr(&viol_f, 1);
    __syncthreads();
    if (threadIdx.x == 0)
        g_mask_mode = (!viol_f) ? 2 : ((!viol_i) ? 1 : 0);
}

// h0 is (HID, NV); broadcast to all batches into [b][v][hid] layout.
__global__ void init_h_kernel(const float* __restrict__ h0) {
    int idx = blockIdx.x * blockDim.x + threadIdx.x;
    int hh = idx % HID;
    int v  = (idx / HID) % NV;
    int b  = idx / (HID * NV);
    g_h[0][b][v][hh] = h0[hh * NV + v];
}

// ---------------------------------------------------------------------------
// One fused kernel per time step.
// Grid: (16 w-tiles, 8 batches). Block: 256 threads.
// Each block computes, for its (b, w-tile of 64 nodes):
//   h_diff[64 hid][64 w]  (GEMM over K=1024, shared-memory tiled)
//   x_hat (recomputed per block from the h tiles it streams anyway)
//   x_g[64 w]             (vec-mat over K=1024)
//   GRU gates, h_new, reprs/imps/preds outputs, next-step state.
// ---------------------------------------------------------------------------
__global__ void __launch_bounds__(256, 1) step_kernel(
    int t, int cur,
    const float* __restrict__ x, const unsigned char* __restrict__ mask_raw,
    const float* __restrict__ graph, const float* __restrict__ ind_graph,
    const float* __restrict__ W_init, const float* __restrict__ b_init,
    const float* __restrict__ W_out,  const float* __restrict__ b_out,
    const float* __restrict__ W_ih,   const float* __restrict__ W_hh,
    const float* __restrict__ b_ih,   const float* __restrict__ b_hh,
    float* __restrict__ out_imps, float* __restrict__ out_preds,
    float* __restrict__ out_reprs)
{
    __shared__ __align__(16) float bufA[KC * PAD]; // h tile [v][hid]; later h_new [hid][w]
    __shared__ __align__(16) float bufB[KC * PAD]; // graph^T tile [v][w]; later h_diff [hid][w]
    __shared__ float sh_x[KC];
    __shared__ float sh_xg[TW];

    const int tid = threadIdx.x;
    const int wt  = blockIdx.x;      // w-tile index 0..15
    const int b   = blockIdx.y;
    const int w0  = wt * TW;
    const int mode = g_mask_mode;
    const int nxt  = cur ^ 1;

    const float* hbase = &g_h[cur][b][0][0];   // contiguous [NV][HID]

    const int hq = tid >> 4;   // 0..15: owns hid rows 4hq..4hq+3
    const int wq = tid & 15;   // 0..15: owns w cols  4wq..4wq+3

    float acc[4][4];
    #pragma unroll
    for (int j = 0; j < 4; j++)
        #pragma unroll
        for (int i = 0; i < 4; i++) acc[j][i] = 0.f;
    float xg_acc = 0.f;

    for (int v0 = 0; v0 < NV; v0 += KC) {
        __syncthreads();   // protect bufA/bufB from previous iteration readers
        // load h tile: bufA[v][hh]  (global reads fully coalesced: contiguous chunk)
        #pragma unroll
        for (int r = 0; r < (KC * HID) / 256; r++) {
            int idx = tid + r * 256;
            int vv = idx >> 6, hhh = idx & 63;
            bufA[vv * PAD + hhh] = hbase[v0 * HID + idx];
        }
        // load graph tile transposed: bufB[v][w] = graph[w0+w][v0+v]
        #pragma unroll
        for (int r = 0; r < (KC * TW) / 256; r++) {
            int idx = tid + r * 256;
            int w = idx >> 6, vv = idx & 63;
            bufB[vv * PAD + w] = graph[(w0 + w) * NV + v0 + vv];
        }
        __syncthreads();

        if (tid < KC) {
            // x_hat1 / x_hat for node v0+tid (uses the h tile already in shared)
            float d = 0.f;
            #pragma unroll 16
            for (int hh = 0; hh < HID; hh++) d += W_init[hh] * bufA[tid * PAD + hh];
            d += b_init[0];
            int gv = v0 + tid;
            int xi = (b * NV + gv) * NT + t;
            bool m;
            if (mode == 0)      m = mask_raw[xi] != 0;
            else if (mode == 1) m = ((const int*)mask_raw)[xi] != 0;
            else                m = ((const float*)mask_raw)[xi] != 0.f;
            sh_x[tid] = m ? x[xi] : d;
            if (wt == 0) out_preds[xi] = d;   // preds = pre-mask x_hat1; one writer tile
        }
        __syncthreads();

        // GEMM accumulate: acc[j][i] += graph[w0+4wq+j][v] * h[b][4hq+i][v]
        #pragma unroll 8
        for (int v = 0; v < KC; v++) {
            float4 av  = *(const float4*)&bufA[v * PAD + 4 * hq];
            float4 gv4 = *(const float4*)&bufB[v * PAD + 4 * wq];
            float a[4] = {av.x, av.y, av.z, av.w};
            float g[4] = {gv4.x, gv4.y, gv4.z, gv4.w};
            #pragma unroll
            for (int j = 0; j < 4; j++)
                #pragma unroll
                for (int i = 0; i < 4; i++)
                    acc[j][i] += g[j] * a[i];
        }
        // x_g accumulation (64 threads, one node each; ind_graph rows stay hot in L2)
        if (tid < TW) {
            const float* ig = &ind_graph[(w0 + tid) * NV + v0];
            float s = 0.f;
            #pragma unroll 16
            for (int v = 0; v < KC; v++) s += sh_x[v] * __ldg(&ig[v]);
            xg_acc += s;
        }
    }
    __syncthreads();

    // spill h_diff into bufB as [hid][w]
    #pragma unroll
    for (int j = 0; j < 4; j++)
        #pragma unroll
        for (int i = 0; i < 4; i++)
            bufB[(4 * hq + i) * PAD + (4 * wq + j)] = acc[j][i];
    if (tid < TW) sh_xg[tid] = xg_acc;
    __syncthreads();

    // GRU gates: thread owns one hid output, 16 nodes
    {
        int hh = tid >> 2;
        int wg = tid & 3;
        float wih_r = W_ih[hh], wih_z = W_ih[64 + hh], wih_n = W_ih[128 + hh];
        float bih_r = b_ih[hh], bih_z = b_ih[64 + hh], bih_n = b_ih[128 + hh];
        float bhh_r = b_hh[hh], bhh_z = b_hh[64 + hh], bhh_n = b_hh[128 + hh];
        const float* Wr = &W_hh[hh * HID];
        const float* Wz = &W_hh[(64 + hh) * HID];
        const float* Wn = &W_hh[(128 + hh) * HID];
        for (int k = 0; k < 16; k++) {
            int w = wg + 4 * k;
            float hr = bhh_r, hz = bhh_z, hn = bhh_n;
            #pragma unroll 16
            for (int j = 0; j < HID; j++) {
                float hdv = bufB[j * PAD + w];
                hr += Wr[j] * hdv;
                hz += Wz[j] * hdv;
                hn += Wn[j] * hdv;
            }
            float xg = sh_xg[w];
            float r = 1.f / (1.f + expf(-(wih_r * xg + bih_r + hr)));
            float z = 1.f / (1.f + expf(-(wih_z * xg + bih_z + hz)));
            float n = tanhf(wih_n * xg + bih_n + r * hn);
            float hd_self = bufB[hh * PAD + w];
            float hnew = (1.f - z) * n + z * hd_self;
            g_h[nxt][b][w0 + w][hh] = hnew;
            out_reprs[((b * HID + hh) * NV + (w0 + w)) * NT + t] = hnew;
            bufA[hh * PAD + w] = hnew;   // stash for x_hat2 dot
        }
    }
    __syncthreads();

    // x_hat2 (imps): 64-dot per node over h_new
    if (tid < TW) {
        int w = tid;
        float d = 0.f;
        #pragma unroll 16
        for (int hh = 0; hh < HID; hh++) d += W_out[hh] * bufA[hh * PAD + w];
        out_imps[(b * NV + w0 + w) * NT + t] = d + b_out[0];
    }
}

extern "C" void kernel_launch(void* const* d_in, const int* in_sizes, int n_in,
                              void* d_out, int out_size) {
    const float* x          = (const float*)d_in[0];
    const unsigned char* mk = (const unsigned char*)d_in[1];
    const float* graph      = (const float*)d_in[2];
    const float* ind_graph  = (const float*)d_in[3];
    const float* h0         = (const float*)d_in[4];
    const float* W_init     = (const float*)d_in[5];
    const float* b_init     = (const float*)d_in[6];
    const float* W_out      = (const float*)d_in[7];
    const float* b_out      = (const float*)d_in[8];
    const float* W_ih       = (const float*)d_in[9];
    const float* W_hh       = (const float*)d_in[10];
    const float* b_ih       = (const float*)d_in[11];
    const float* b_hh       = (const float*)d_in[12];

    float* out_imps  = (float*)d_out;                  // (8,1,1024,64)
    float* out_preds = out_imps + BSZ * NV * NT;       // (8,1,1024,64)
    float* out_reprs = out_preds + BSZ * NV * NT;      // (8,64,1024,64)

    detect_mask_kernel<<<1, 256>>>((const unsigned int*)mk);
    init_h_kernel<<<(BSZ * NV * HID) / 256, 256>>>(h0);
    for (int t = 0; t < NT; t++) {
        step_kernel<<<dim3(16, BSZ), 256>>>(
            t, t & 1, x, mk, graph, ind_graph,
            W_init, b_init, W_out, b_out, W_ih, W_hh, b_ih, b_hh,
            out_imps, out_preds, out_reprs);
    }
}

// round 3
// speedup vs baseline: 3.1693x; 3.1693x over previous
#include <cuda_runtime.h>
#include <cstdint>

#define BSZ 8
#define HID 64
#define NV  1024
#define NT  64
#define TW  64
#define KC  64
#define PADG 65

// Recurrent state ping-pong [buf][b][v][hid]; masked x_hat; transposed graph.
__device__ float g_h[2][BSZ][NV][HID];
__device__ float g_xh[BSZ][NV];
__device__ float g_graphT[NV * NV];   // g_graphT[v*NV + w] = graph[w*NV + v]
__device__ int   g_mask_mode;         // 0=byte, 1=int32, 2=float32

// ---------------------------------------------------------------------------
__device__ __forceinline__ void cp_async16(void* s, const void* g) {
    uint32_t sa = (uint32_t)__cvta_generic_to_shared(s);
    asm volatile("cp.async.ca.shared.global [%0], [%1], 16;" :: "r"(sa), "l"(g));
}
__device__ __forceinline__ void cp_commit() { asm volatile("cp.async.commit_group;"); }
__device__ __forceinline__ void cp_wait0()  { asm volatile("cp.async.wait_group 0;"); }

// ---------------------------------------------------------------------------
__global__ void detect_mask_kernel(const unsigned int* __restrict__ m) {
    __shared__ int viol_i, viol_f;
    if (threadIdx.x == 0) { viol_i = 0; viol_f = 0; }
    __syncthreads();
    int li = 0, lf = 0;
    const int nwords = (BSZ * NV * NT) / 4;
    for (int i = threadIdx.x; i < nwords; i += blockDim.x) {
        unsigned int w = m[i];
        if (w > 1u) li = 1;
        if (w != 0u && w != 0x3F800000u) lf = 1;
    }
    if (li) atomicOr(&viol_i, 1);
    if (lf) atomicOr(&viol_f, 1);
    __syncthreads();
    if (threadIdx.x == 0)
        g_mask_mode = (!viol_f) ? 2 : ((!viol_i) ? 1 : 0);
}

// ---------------------------------------------------------------------------
__global__ void init_h_kernel(const float* __restrict__ h0) {
    int idx = blockIdx.x * blockDim.x + threadIdx.x;
    int hh = idx % HID;
    int v  = (idx / HID) % NV;
    int b  = idx / (HID * NV);
    g_h[0][b][v][hh] = h0[hh * NV + v];
}

// ---------------------------------------------------------------------------
__global__ void transpose_graph_kernel(const float* __restrict__ graph) {
    __shared__ float tile[32][33];
    int bx = blockIdx.x * 32, by = blockIdx.y * 32;
    int tx = threadIdx.x, ty = threadIdx.y;   // block (32, 8)
    #pragma unroll
    for (int r = 0; r < 32; r += 8)
        tile[ty + r][tx] = graph[(by + ty + r) * NV + bx + tx];
    __syncthreads();
    #pragma unroll
    for (int r = 0; r < 32; r += 8)
        g_graphT[(bx + ty + r) * NV + by + tx] = tile[tx][ty + r];
}

// ---------------------------------------------------------------------------
// Per step: x_hat1 = W_init·h + b; preds out; g_xh = mask ? x : x_hat1.
// Grid (16, 8), 256 threads: thread quad per node.
// ---------------------------------------------------------------------------
__global__ void prep_kernel(int t, int cur,
    const float* __restrict__ x, const unsigned char* __restrict__ mask_raw,
    const float* __restrict__ W_init, const float* __restrict__ b_init,
    float* __restrict__ out_preds)
{
    int b = blockIdx.y;
    int v = blockIdx.x * 64 + (threadIdx.x >> 2);
    int q = threadIdx.x & 3;
    const float4* h4 = (const float4*)&g_h[cur][b][v][0] + q * 4;
    const float4* w4 = (const float4*)W_init + q * 4;
    float part = 0.f;
    #pragma unroll
    for (int j = 0; j < 4; j++) {
        float4 a = h4[j], w = w4[j];
        part += a.x * w.x + a.y * w.y + a.z * w.z + a.w * w.w;
    }
    part += __shfl_xor_sync(0xffffffffu, part, 1);
    part += __shfl_xor_sync(0xffffffffu, part, 2);
    if (q == 0) {
        float d = part + b_init[0];
        int xi = (b * NV + v) * NT + t;
        int mode = g_mask_mode;
        bool m;
        if (mode == 0)      m = mask_raw[xi] != 0;
        else if (mode == 1) m = ((const int*)mask_raw)[xi] != 0;
        else                m = ((const float*)mask_raw)[xi] != 0.f;
        g_xh[b][v] = m ? x[xi] : d;
        out_preds[xi] = d;
    }
}

// ---------------------------------------------------------------------------
// Main step: grid (16 w-tiles, 8 batches), 256 threads, dynamic smem.
// Phase A: x_g (all threads) overlapped with cp.async of GEMM tile 0.
// Phase B: h_diff GEMM, double-buffered, 1 barrier per k-tile.
// Phase C: GRU gates (register-accumulated), outputs.
// ---------------------------------------------------------------------------
__global__ void __launch_bounds__(256, 1) step_kernel(int t, int cur,
    const float* __restrict__ ind_graph,
    const float* __restrict__ W_out, const float* __restrict__ b_out,
    const float* __restrict__ W_ih,  const float* __restrict__ W_hh,
    const float* __restrict__ b_ih,  const float* __restrict__ b_hh,
    float* __restrict__ out_imps, float* __restrict__ out_reprs)
{
    extern __shared__ float smem[];
    float* bufA   = smem;                 // 2 x [64 v][64 hid] = 8192
    float* bufB   = smem + 2 * 4096;      // 2 x [64 v][64 w]   = 8192
    float* bufG   = smem + 4 * 4096;      // h_diff [64 hid][PADG] = 4160
    float* sh_xg  = bufG + KC * PADG;     // 64
    float* sh_part= sh_xg + TW;           // 256
    float* hn_sm  = bufA;                 // reused after GEMM: h_new [hh][PADG]

    const int tid = threadIdx.x;
    const int wt  = blockIdx.x;
    const int b   = blockIdx.y;
    const int w0  = wt * TW;
    const int nxt = cur ^ 1;
    const float* hbase = &g_h[cur][b][0][0];

    // ---- issue cp.async for GEMM tile 0 (buffer 0) ----
    {
        #pragma unroll
        for (int r = 0; r < 4; r++) {
            int c = r * 256 + tid;                       // 0..1023 16B chunks
            cp_async16(bufA + c * 4, hbase + c * 4);     // tile kt=0
            int row = c >> 4, col = c & 15;
            cp_async16(bufB + row * 64 + col * 4,
                       &g_graphT[row * NV + w0 + col * 4]);
        }
        cp_commit();
    }

    // ---- Phase A: x_g[w] = sum_v g_xh[b][v] * ind_graph[w0+w][v] ----
    {
        int w = tid & 63, q = tid >> 6;
        const float4* ig = (const float4*)&ind_graph[(w0 + w) * NV + q * 256];
        const float4* xh = (const float4*)&g_xh[b][q * 256];
        float s = 0.f;
        #pragma unroll 16
        for (int j = 0; j < 64; j++) {
            float4 a = ig[j], c = xh[j];
            s += a.x * c.x + a.y * c.y + a.z * c.z + a.w * c.w;
        }
        sh_part[q * 64 + w] = s;
    }
    __syncthreads();
    if (tid < TW)
        sh_xg[tid] = sh_part[tid] + sh_part[64 + tid] + sh_part[128 + tid] + sh_part[192 + tid];
    cp_wait0();
    __syncthreads();   // tile 0 ready; sh_xg ready

    // ---- Phase B: GEMM h_diff[hid][w] over K=1024, double-buffered ----
    const int hq = tid >> 4;   // 4 hid rows 4hq..
    const int wq = tid & 15;   // 4 w cols  4wq..
    float acc[4][4];
    #pragma unroll
    for (int j = 0; j < 4; j++)
        #pragma unroll
        for (int i = 0; i < 4; i++) acc[j][i] = 0.f;

    int p = 0;
    for (int kt = 0; kt < 16; kt++) {
        if (kt < 15) {   // prefetch next tile into buffer p^1
            float* dA = bufA + (p ^ 1) * 4096;
            float* dB = bufB + (p ^ 1) * 4096;
            const float* sA = hbase + (kt + 1) * 4096;
            const float* sB = g_graphT + (kt + 1) * 64 * NV + w0;
            #pragma unroll
            for (int r = 0; r < 4; r++) {
                int c = r * 256 + tid;
                cp_async16(dA + c * 4, sA + c * 4);
                int row = c >> 4, col = c & 15;
                cp_async16(dB + row * 64 + col * 4, sB + row * NV + col * 4);
            }
            cp_commit();
        }
        const float* A = bufA + p * 4096;
        const float* B = bufB + p * 4096;
        #pragma unroll 8
        for (int v = 0; v < KC; v++) {
            float4 av = *(const float4*)&A[v * 64 + 4 * hq];
            float4 gv = *(const float4*)&B[v * 64 + 4 * wq];
            float a[4] = {av.x, av.y, av.z, av.w};
            float g[4] = {gv.x, gv.y, gv.z, gv.w};
            #pragma unroll
            for (int j = 0; j < 4; j++)
                #pragma unroll
                for (int i = 0; i < 4; i++)
                    acc[j][i] += g[j] * a[i];
        }
        if (kt < 15) cp_wait0();
        __syncthreads();
        p ^= 1;
    }

    // spill h_diff -> bufG [hid][w]
    #pragma unroll
    for (int j = 0; j < 4; j++)
        #pragma unroll
        for (int i = 0; i < 4; i++)
            bufG[(4 * hq + i) * PADG + 4 * wq + j] = acc[j][i];
    __syncthreads();

    // ---- Phase C: GRU gates. Thread = (hh, wg), 16 nodes each. ----
    {
        const int hh = tid >> 2;
        const int wg = tid & 3;
        float ar[16], az[16], an[16];
        #pragma unroll
        for (int k = 0; k < 16; k++) { ar[k] = 0.f; az[k] = 0.f; an[k] = 0.f; }
        const float* Wr = &W_hh[hh * HID];
        const float* Wz = &W_hh[(64 + hh) * HID];
        const float* Wn = &W_hh[(128 + hh) * HID];
        #pragma unroll 4
        for (int j = 0; j < HID; j++) {
            float wr = Wr[j], wz = Wz[j], wn = Wn[j];
            const float* row = &bufG[j * PADG + wg];
            #pragma unroll
            for (int k = 0; k < 16; k++) {
                float hd = row[4 * k];
                ar[k] += wr * hd; az[k] += wz * hd; an[k] += wn * hd;
            }
        }
        float wih_r = W_ih[hh],  wih_z = W_ih[64 + hh],  wih_n = W_ih[128 + hh];
        float bi_r  = b_ih[hh] + b_hh[hh];
        float bi_z  = b_ih[64 + hh] + b_hh[64 + hh];
        float bi_n  = b_ih[128 + hh];
        float bh_n  = b_hh[128 + hh];
        #pragma unroll
        for (int k = 0; k < 16; k++) {
            int w = wg + 4 * k;
            float xg = sh_xg[w];
            float r = 1.f / (1.f + __expf(-(ar[k] + wih_r * xg + bi_r)));
            float z = 1.f / (1.f + __expf(-(az[k] + wih_z * xg + bi_z)));
            float n = tanhf(wih_n * xg + bi_n + r * (an[k] + bh_n));
            float hd_self = bufG[hh * PADG + w];
            float hnew = (1.f - z) * n + z * hd_self;
            g_h[nxt][b][w0 + w][hh] = hnew;
            out_reprs[((b * HID + hh) * NV + (w0 + w)) * NT + t] = hnew;
            hn_sm[hh * PADG + w] = hnew;
        }
    }
    __syncthreads();

    // ---- imps = W_out · h_new + b_out ----
    {
        int w = tid & 63, q = tid >> 6;
        float s = 0.f;
        #pragma unroll
        for (int j = 0; j < 16; j++) {
            int hh = q * 16 + j;
            s += W_out[hh] * hn_sm[hh * PADG + w];
        }
        sh_part[q * 64 + w] = s;
    }
    __syncthreads();
    if (tid < TW) {
        float d = sh_part[tid] + sh_part[64 + tid] + sh_part[128 + tid] + sh_part[192 + tid];
        out_imps[(b * NV + w0 + tid) * NT + t] = d + b_out[0];
    }
}

// ---------------------------------------------------------------------------
extern "C" void kernel_launch(void* const* d_in, const int* in_sizes, int n_in,
                              void* d_out, int out_size) {
    const float* x          = (const float*)d_in[0];
    const unsigned char* mk = (const unsigned char*)d_in[1];
    const float* graph      = (const float*)d_in[2];
    const float* ind_graph  = (const float*)d_in[3];
    const float* h0         = (const float*)d_in[4];
    const float* W_init     = (const float*)d_in[5];
    const float* b_init     = (const float*)d_in[6];
    const float* W_out      = (const float*)d_in[7];
    const float* b_out      = (const float*)d_in[8];
    const float* W_ih       = (const float*)d_in[9];
    const float* W_hh       = (const float*)d_in[10];
    const float* b_ih       = (const float*)d_in[11];
    const float* b_hh       = (const float*)d_in[12];

    float* out_imps  = (float*)d_out;
    float* out_preds = out_imps + BSZ * NV * NT;
    float* out_reprs = out_preds + BSZ * NV * NT;

    const int smem_bytes = (2 * 4096 + 2 * 4096 + KC * PADG + TW + 256) * 4;
    cudaFuncSetAttribute(step_kernel, cudaFuncAttributeMaxDynamicSharedMemorySize,
                         smem_bytes);

    detect_mask_kernel<<<1, 256>>>((const unsigned int*)mk);
    transpose_graph_kernel<<<dim3(32, 32), dim3(32, 8)>>>(graph);
    init_h_kernel<<<(BSZ * NV * HID) / 256, 256>>>(h0);
    for (int t = 0; t < NT; t++) {
        prep_kernel<<<dim3(16, BSZ), 256>>>(t, t & 1, x, mk, W_init, b_init, out_preds);
        step_kernel<<<dim3(16, BSZ), 256, smem_bytes>>>(
            t, t & 1, ind_graph, W_out, b_out, W_ih, W_hh, b_ih, b_hh,
            out_imps, out_reprs);
    }
}

// round 4
// speedup vs baseline: 3.2618x; 1.0292x over previous
#include <cuda_runtime.h>
#include <cstdint>

#define BSZ 8
#define HID 64
#define NV  1024
#define NT  64
#define TW  64
#define KC  64
#define PADG 65

// Recurrent state ping-pong [buf][b][v][hid]; masked x_hat; transposed graph.
__device__ float g_h[2][BSZ][NV][HID];
__device__ float g_xh[BSZ][NV];
__device__ float g_graphT[NV * NV];   // g_graphT[v*NV + w] = graph[w*NV + v]
__device__ int   g_mask_mode;         // 0=byte, 1=int32, 2=float32

// ---------------------------------------------------------------------------
__device__ __forceinline__ void cp_async16(void* s, const void* g) {
    uint32_t sa = (uint32_t)__cvta_generic_to_shared(s);
    asm volatile("cp.async.ca.shared.global [%0], [%1], 16;" :: "r"(sa), "l"(g));
}
__device__ __forceinline__ void cp_commit() { asm volatile("cp.async.commit_group;"); }
__device__ __forceinline__ void cp_wait0()  { asm volatile("cp.async.wait_group 0;"); }
__device__ __forceinline__ void stcs(float* p, float v) {
    asm volatile("st.global.cs.f32 [%0], %1;" :: "l"(p), "f"(v));
}

// ---------------------------------------------------------------------------
__global__ void detect_mask_kernel(const unsigned int* __restrict__ m) {
    __shared__ int viol_i, viol_f;
    if (threadIdx.x == 0) { viol_i = 0; viol_f = 0; }
    __syncthreads();
    int li = 0, lf = 0;
    const int nwords = (BSZ * NV * NT) / 4;
    for (int i = threadIdx.x; i < nwords; i += blockDim.x) {
        unsigned int w = m[i];
        if (w > 1u) li = 1;
        if (w != 0u && w != 0x3F800000u) lf = 1;
    }
    if (li) atomicOr(&viol_i, 1);
    if (lf) atomicOr(&viol_f, 1);
    __syncthreads();
    if (threadIdx.x == 0)
        g_mask_mode = (!viol_f) ? 2 : ((!viol_i) ? 1 : 0);
}

// ---------------------------------------------------------------------------
__global__ void init_h_kernel(const float* __restrict__ h0) {
    int idx = blockIdx.x * blockDim.x + threadIdx.x;
    int hh = idx % HID;
    int v  = (idx / HID) % NV;
    int b  = idx / (HID * NV);
    g_h[0][b][v][hh] = h0[hh * NV + v];
}

// ---------------------------------------------------------------------------
__global__ void transpose_graph_kernel(const float* __restrict__ graph) {
    __shared__ float tile[32][33];
    int bx = blockIdx.x * 32, by = blockIdx.y * 32;
    int tx = threadIdx.x, ty = threadIdx.y;   // block (32, 8)
    #pragma unroll
    for (int r = 0; r < 32; r += 8)
        tile[ty + r][tx] = graph[(by + ty + r) * NV + bx + tx];
    __syncthreads();
    #pragma unroll
    for (int r = 0; r < 32; r += 8)
        g_graphT[(bx + ty + r) * NV + by + tx] = tile[tx][ty + r];
}

// ---------------------------------------------------------------------------
// One-time prep for t=0: x_hat1 = W_init·h0 + b; preds[0]; g_xh.
// Grid (16, 8), 256 threads: thread quad per node.
// ---------------------------------------------------------------------------
__global__ void prep_kernel(
    const float* __restrict__ x, const unsigned char* __restrict__ mask_raw,
    const float* __restrict__ W_init, const float* __restrict__ b_init,
    float* __restrict__ out_preds)
{
    int b = blockIdx.y;
    int v = blockIdx.x * 64 + (threadIdx.x >> 2);
    int q = threadIdx.x & 3;
    const float4* h4 = (const float4*)&g_h[0][b][v][0] + q * 4;
    const float4* w4 = (const float4*)W_init + q * 4;
    float part = 0.f;
    #pragma unroll
    for (int j = 0; j < 4; j++) {
        float4 a = h4[j], w = w4[j];
        part += a.x * w.x + a.y * w.y + a.z * w.z + a.w * w.w;
    }
    part += __shfl_xor_sync(0xffffffffu, part, 1);
    part += __shfl_xor_sync(0xffffffffu, part, 2);
    if (q == 0) {
        float d = part + b_init[0];
        int xi = (b * NV + v) * NT + 0;
        int mode = g_mask_mode;
        bool m;
        if (mode == 0)      m = mask_raw[xi] != 0;
        else if (mode == 1) m = ((const int*)mask_raw)[xi] != 0;
        else                m = ((const float*)mask_raw)[xi] != 0.f;
        g_xh[b][v] = m ? x[xi] : d;
        out_preds[xi] = d;
    }
}

// ---------------------------------------------------------------------------
// Main step: grid (16 w-tiles, 8 batches), 256 threads, dynamic smem.
// Phase A: x_g (all threads) overlapped with cp.async of GEMM tile 0.
// Phase B: h_diff GEMM, double-buffered, 1 barrier per k-tile.
// Phase C: GRU gates (register-accumulated), h_new.
// Phase D: fused epilogue — imps(t) AND prep for t+1 (preds, g_xh) in one pass.
// ---------------------------------------------------------------------------
__global__ void __launch_bounds__(256, 1) step_kernel(int t, int cur,
    const float* __restrict__ x, const unsigned char* __restrict__ mask_raw,
    const float* __restrict__ ind_graph,
    const float* __restrict__ W_init, const float* __restrict__ b_init,
    const float* __restrict__ W_out,  const float* __restrict__ b_out,
    const float* __restrict__ W_ih,   const float* __restrict__ W_hh,
    const float* __restrict__ b_ih,   const float* __restrict__ b_hh,
    float* __restrict__ out_imps, float* __restrict__ out_preds,
    float* __restrict__ out_reprs)
{
    extern __shared__ float smem[];
    float* bufA   = smem;                 // 2 x [64 v][64 hid] = 8192
    float* bufB   = smem + 2 * 4096;      // 2 x [64 v][64 w]   = 8192
    float* bufG   = smem + 4 * 4096;      // h_diff [64 hid][PADG] = 4160
    float* sh_xg  = bufG + KC * PADG;     // 64
    float* sh_part= sh_xg + TW;           // 512 (two reductions)
    float* hn_sm  = bufA;                 // reused after GEMM: h_new [hh][PADG]

    const int tid = threadIdx.x;
    const int wt  = blockIdx.x;
    const int b   = blockIdx.y;
    const int w0  = wt * TW;
    const int nxt = cur ^ 1;
    const float* hbase = &g_h[cur][b][0][0];

    // ---- issue cp.async for GEMM tile 0 (buffer 0) ----
    {
        #pragma unroll
        for (int r = 0; r < 4; r++) {
            int c = r * 256 + tid;                       // 0..1023 16B chunks
            cp_async16(bufA + c * 4, hbase + c * 4);     // tile kt=0
            int row = c >> 4, col = c & 15;
            cp_async16(bufB + row * 64 + col * 4,
                       &g_graphT[row * NV + w0 + col * 4]);
        }
        cp_commit();
    }

    // ---- Phase A: x_g[w] = sum_v g_xh[b][v] * ind_graph[w0+w][v] ----
    {
        int w = tid & 63, q = tid >> 6;
        const float4* ig = (const float4*)&ind_graph[(w0 + w) * NV + q * 256];
        const float4* xh = (const float4*)&g_xh[b][q * 256];
        float s = 0.f;
        #pragma unroll 16
        for (int j = 0; j < 64; j++) {
            float4 a = ig[j], c = xh[j];
            s += a.x * c.x + a.y * c.y + a.z * c.z + a.w * c.w;
        }
        sh_part[q * 64 + w] = s;
    }
    __syncthreads();
    if (tid < TW)
        sh_xg[tid] = sh_part[tid] + sh_part[64 + tid] + sh_part[128 + tid] + sh_part[192 + tid];
    cp_wait0();
    __syncthreads();   // tile 0 ready; sh_xg ready

    // ---- Phase B: GEMM h_diff[hid][w] over K=1024, double-buffered ----
    const int hq = tid >> 4;   // 4 hid rows 4hq..
    const int wq = tid & 15;   // 4 w cols  4wq..
    float acc[4][4];
    #pragma unroll
    for (int j = 0; j < 4; j++)
        #pragma unroll
        for (int i = 0; i < 4; i++) acc[j][i] = 0.f;

    int p = 0;
    for (int kt = 0; kt < 16; kt++) {
        if (kt < 15) {   // prefetch next tile into buffer p^1
            float* dA = bufA + (p ^ 1) * 4096;
            float* dB = bufB + (p ^ 1) * 4096;
            const float* sA = hbase + (kt + 1) * 4096;
            const float* sB = g_graphT + (kt + 1) * 64 * NV + w0;
            #pragma unroll
            for (int r = 0; r < 4; r++) {
                int c = r * 256 + tid;
                cp_async16(dA + c * 4, sA + c * 4);
                int row = c >> 4, col = c & 15;
                cp_async16(dB + row * 64 + col * 4, sB + row * NV + col * 4);
            }
            cp_commit();
        }
        const float* A = bufA + p * 4096;
        const float* B = bufB + p * 4096;
        #pragma unroll 8
        for (int v = 0; v < KC; v++) {
            float4 av = *(const float4*)&A[v * 64 + 4 * hq];
            float4 gv = *(const float4*)&B[v * 64 + 4 * wq];
            float a[4] = {av.x, av.y, av.z, av.w};
            float g[4] = {gv.x, gv.y, gv.z, gv.w};
            #pragma unroll
            for (int j = 0; j < 4; j++)
                #pragma unroll
                for (int i = 0; i < 4; i++)
                    acc[j][i] += g[j] * a[i];
        }
        if (kt < 15) cp_wait0();
        __syncthreads();
        p ^= 1;
    }

    // spill h_diff -> bufG [hid][w]
    #pragma unroll
    for (int j = 0; j < 4; j++)
        #pragma unroll
        for (int i = 0; i < 4; i++)
            bufG[(4 * hq + i) * PADG + 4 * wq + j] = acc[j][i];
    __syncthreads();

    // ---- Phase C: GRU gates. Thread = (hh, wg), 16 nodes each. ----
    {
        const int hh = tid >> 2;
        const int wg = tid & 3;
        float ar[16], az[16], an[16];
        #pragma unroll
        for (int k = 0; k < 16; k++) { ar[k] = 0.f; az[k] = 0.f; an[k] = 0.f; }
        const float* Wr = &W_hh[hh * HID];
        const float* Wz = &W_hh[(64 + hh) * HID];
        const float* Wn = &W_hh[(128 + hh) * HID];
        #pragma unroll 4
        for (int j = 0; j < HID; j++) {
            float wr = Wr[j], wz = Wz[j], wn = Wn[j];
            const float* row = &bufG[j * PADG + wg];
            #pragma unroll
            for (int k = 0; k < 16; k++) {
                float hd = row[4 * k];
                ar[k] += wr * hd; az[k] += wz * hd; an[k] += wn * hd;
            }
        }
        float wih_r = W_ih[hh],  wih_z = W_ih[64 + hh],  wih_n = W_ih[128 + hh];
        float bi_r  = b_ih[hh] + b_hh[hh];
        float bi_z  = b_ih[64 + hh] + b_hh[64 + hh];
        float bi_n  = b_ih[128 + hh];
        float bh_n  = b_hh[128 + hh];
        #pragma unroll
        for (int k = 0; k < 16; k++) {
            int w = wg + 4 * k;
            float xg = sh_xg[w];
            float r = 1.f / (1.f + __expf(-(ar[k] + wih_r * xg + bi_r)));
            float z = 1.f / (1.f + __expf(-(az[k] + wih_z * xg + bi_z)));
            float n = tanhf(wih_n * xg + bi_n + r * (an[k] + bh_n));
            float hd_self = bufG[hh * PADG + w];
            float hnew = (1.f - z) * n + z * hd_self;
            g_h[nxt][b][w0 + w][hh] = hnew;
            stcs(&out_reprs[((b * HID + hh) * NV + (w0 + w)) * NT + t], hnew);
            hn_sm[hh * PADG + w] = hnew;
        }
    }
    __syncthreads();

    // ---- Phase D: fused epilogue. One pass over h_new computes both
    //      imps(t) = W_out·h_new + b_out and x_hat1(t+1) = W_init·h_new + b_init.
    {
        int w = tid & 63, q = tid >> 6;
        float so = 0.f, si = 0.f;
        #pragma unroll
        for (int j = 0; j < 16; j++) {
            int hh = q * 16 + j;
            float hv = hn_sm[hh * PADG + w];
            so += W_out[hh]  * hv;
            si += W_init[hh] * hv;
        }
        sh_part[q * 64 + w]       = so;
        sh_part[256 + q * 64 + w] = si;
    }
    __syncthreads();
    if (tid < TW) {
        int w = tid;
        float so = sh_part[w] + sh_part[64 + w] + sh_part[128 + w] + sh_part[192 + w];
        stcs(&out_imps[(b * NV + w0 + w) * NT + t], so + b_out[0]);
        if (t < NT - 1) {
            float si = sh_part[256 + w] + sh_part[320 + w] + sh_part[384 + w] + sh_part[448 + w];
            float d = si + b_init[0];
            int gv = w0 + w;
            int xi = (b * NV + gv) * NT + (t + 1);
            int mode = g_mask_mode;
            bool m;
            if (mode == 0)      m = mask_raw[xi] != 0;
            else if (mode == 1) m = ((const int*)mask_raw)[xi] != 0;
            else                m = ((const float*)mask_raw)[xi] != 0.f;
            g_xh[b][gv] = m ? x[xi] : d;
            stcs(&out_preds[xi], d);
        }
    }
}

// ---------------------------------------------------------------------------
extern "C" void kernel_launch(void* const* d_in, const int* in_sizes, int n_in,
                              void* d_out, int out_size) {
    const float* x          = (const float*)d_in[0];
    const unsigned char* mk = (const unsigned char*)d_in[1];
    const float* graph      = (const float*)d_in[2];
    const float* ind_graph  = (const float*)d_in[3];
    const float* h0         = (const float*)d_in[4];
    const float* W_init     = (const float*)d_in[5];
    const float* b_init     = (const float*)d_in[6];
    const float* W_out      = (const float*)d_in[7];
    const float* b_out      = (const float*)d_in[8];
    const float* W_ih       = (const float*)d_in[9];
    const float* W_hh       = (const float*)d_in[10];
    const float* b_ih       = (const float*)d_in[11];
    const float* b_hh       = (const float*)d_in[12];

    float* out_imps  = (float*)d_out;
    float* out_preds = out_imps + BSZ * NV * NT;
    float* out_reprs = out_preds + BSZ * NV * NT;

    const int smem_bytes = (2 * 4096 + 2 * 4096 + KC * PADG + TW + 512) * 4;
    cudaFuncSetAttribute(step_kernel, cudaFuncAttributeMaxDynamicSharedMemorySize,
                         smem_bytes);

    detect_mask_kernel<<<1, 256>>>((const unsigned int*)mk);
    transpose_graph_kernel<<<dim3(32, 32), dim3(32, 8)>>>(graph);
    init_h_kernel<<<(BSZ * NV * HID) / 256, 256>>>(h0);
    prep_kernel<<<dim3(16, BSZ), 256>>>(x, mk, W_init, b_init, out_preds);
    for (int t = 0; t < NT; t++) {
        step_kernel<<<dim3(16, BSZ), 256, smem_bytes>>>(
            t, t & 1, x, mk, ind_graph,
            W_init, b_init, W_out, b_out, W_ih, W_hh, b_ih, b_hh,
            out_imps, out_preds, out_reprs);
    }
}

// round 6
// speedup vs baseline: 5.0343x; 1.5434x over previous
#include <cuda_runtime.h>
#include <cuda_bf16.h>
#include <mma.h>
#include <cstdint>

using namespace nvcuda;

#define BSZ 8
#define HID 64
#define NV  1024
#define NT  64

// bf16 hi/lo split state [buf][(b*64+hid)*NV + v]
__device__ __nv_bfloat16 g_hh[2][BSZ * HID * NV];
__device__ __nv_bfloat16 g_hl[2][BSZ * HID * NV];
__device__ __nv_bfloat16 g_gh[NV * NV];       // graph hi  [w][v]
__device__ __nv_bfloat16 g_gl[NV * NV];       // graph lo
__device__ __nv_bfloat16 g_whh_h[192 * 64];   // W_hh hi [gate][hid]
__device__ __nv_bfloat16 g_whh_l[192 * 64];
__device__ float g_xh[BSZ][NV];
__device__ int   g_mask_mode;                 // 0=byte, 1=int32, 2=float32

// smem byte offsets (buffers aliased after GEMM)
#define OFF_AH(b) ((b) * 9216)
#define OFF_AL(b) (18432 + (b) * 9216)
#define OFF_BH(b) (36864 + (b) * 9216)
#define OFF_BL(b) (55296 + (b) * 9216)
#define OFF_HD   0          // f32 [64][72]  (aliases AH)
#define OFF_HDH  18432      // bf16 [64][72] (aliases AL)
#define OFF_HDL  27648
#define OFF_GD   73728      // f32 [192][72]
#define OFF_HN   129024     // f32 [64][72]
#define OFF_XG   147456     // f32 [64]
#define OFF_PART 147712     // f32 [512]
#define SMEM_TOTAL 149760

// ---------------------------------------------------------------------------
__device__ __forceinline__ void cp_async16(uint32_t s, const void* g) {
    asm volatile("cp.async.ca.shared.global [%0], [%1], 16;" :: "r"(s), "l"(g));
}
__device__ __forceinline__ void cp_commit() { asm volatile("cp.async.commit_group;"); }
__device__ __forceinline__ void cp_wait0()  { asm volatile("cp.async.wait_group 0;"); }
__device__ __forceinline__ void cp_wait1()  { asm volatile("cp.async.wait_group 1;"); }
__device__ __forceinline__ void stcs(float* p, float v) {
    asm volatile("st.global.cs.f32 [%0], %1;" :: "l"(p), "f"(v));
}

// ---------------------------------------------------------------------------
__global__ void detect_mask_kernel(const unsigned int* __restrict__ m) {
    __shared__ int viol_i, viol_f;
    if (threadIdx.x == 0) { viol_i = 0; viol_f = 0; }
    __syncthreads();
    int li = 0, lf = 0;
    const int nwords = (BSZ * NV * NT) / 4;
    for (int i = threadIdx.x; i < nwords; i += blockDim.x) {
        unsigned int w = m[i];
        if (w > 1u) li = 1;
        if (w != 0u && w != 0x3F800000u) lf = 1;
    }
    if (li) atomicOr(&viol_i, 1);
    if (lf) atomicOr(&viol_f, 1);
    __syncthreads();
    if (threadIdx.x == 0)
        g_mask_mode = (!viol_f) ? 2 : ((!viol_i) ? 1 : 0);
}

__global__ void split_graph_kernel(const float* __restrict__ graph) {
    int i = blockIdx.x * blockDim.x + threadIdx.x;
    float v = graph[i];
    __nv_bfloat16 hi = __float2bfloat16(v);
    g_gh[i] = hi;
    g_gl[i] = __float2bfloat16(v - __bfloat162float(hi));
}

__global__ void split_whh_kernel(const float* __restrict__ W_hh) {
    int i = blockIdx.x * blockDim.x + threadIdx.x;
    float v = W_hh[i];
    __nv_bfloat16 hi = __float2bfloat16(v);
    g_whh_h[i] = hi;
    g_whh_l[i] = __float2bfloat16(v - __bfloat162float(hi));
}

__global__ void init_h_kernel(const float* __restrict__ h0) {
    int idx = blockIdx.x * blockDim.x + threadIdx.x;   // (b*64+hh)*NV + v
    int v  = idx & (NV - 1);
    int hh = (idx >> 10) & 63;
    float val = h0[hh * NV + v];
    __nv_bfloat16 hi = __float2bfloat16(val);
    g_hh[0][idx] = hi;
    g_hl[0][idx] = __float2bfloat16(val - __bfloat162float(hi));
}

// t=0 prep from h0 directly. Grid (4, 8), 256 threads.
__global__ void prep_kernel(
    const float* __restrict__ x, const unsigned char* __restrict__ mask_raw,
    const float* __restrict__ h0,
    const float* __restrict__ W_init, const float* __restrict__ b_init,
    float* __restrict__ out_preds)
{
    int b = blockIdx.y;
    int v = blockIdx.x * 256 + threadIdx.x;
    float d = 0.f;
    #pragma unroll 16
    for (int hh = 0; hh < HID; hh++) d += W_init[hh] * h0[hh * NV + v];
    d += b_init[0];
    int xi = (b * NV + v) * NT + 0;
    int mode = g_mask_mode;
    bool m;
    if (mode == 0)      m = mask_raw[xi] != 0;
    else if (mode == 1) m = ((const int*)mask_raw)[xi] != 0;
    else                m = ((const float*)mask_raw)[xi] != 0.f;
    g_xh[b][v] = m ? x[xi] : d;
    out_preds[xi] = d;
}

// ---------------------------------------------------------------------------
// Step kernel: grid (16 w-tiles, 8 batches), 256 threads.
//  GEMM  h_diff[64m x 64n] = h[b-rows, 1024k] · graph[w-tile, 1024k]^T
//        via WMMA bf16 3-term split, cp.async double-buffered.
//  Gates gd[192 x 64] = W_hh · h_diff via WMMA bf16 3-term split.
//  Then nonlinearity, state update, fused epilogue (imps t, preds/g_xh t+1).
// ---------------------------------------------------------------------------
__global__ void __launch_bounds__(256) step_tc_kernel(int t, int cur,
    const float* __restrict__ x, const unsigned char* __restrict__ mask_raw,
    const float* __restrict__ ind_graph,
    const float* __restrict__ W_init, const float* __restrict__ b_init,
    const float* __restrict__ W_out,  const float* __restrict__ b_out,
    const float* __restrict__ W_ih,
    const float* __restrict__ b_ih,   const float* __restrict__ b_hh,
    float* __restrict__ out_imps, float* __restrict__ out_preds,
    float* __restrict__ out_reprs)
{
    extern __shared__ __align__(32) char smem[];
    const uint32_t sbase = (uint32_t)__cvta_generic_to_shared(smem);

    const int tid  = threadIdx.x;
    const int wid  = tid >> 5;
    const int wt   = blockIdx.x;
    const int b    = blockIdx.y;          // batch == m-tile
    const int w0   = wt * 64;
    const int m0   = b * 64;
    const int nxt  = cur ^ 1;

    float* hd   = (float*)(smem + OFF_HD);
    __nv_bfloat16* hdh = (__nv_bfloat16*)(smem + OFF_HDH);
    __nv_bfloat16* hdl = (__nv_bfloat16*)(smem + OFF_HDL);
    float* gd   = (float*)(smem + OFF_GD);
    float* hn   = (float*)(smem + OFF_HN);
    float* xg   = (float*)(smem + OFF_XG);
    float* part = (float*)(smem + OFF_PART);

    // fill(kt): cp.async 4 bf16 tiles (Ah, Al, Bh, Bl), 64 rows x 64 cols, ld=72.
    auto fill = [&](int kt) {
        int buf = kt & 1;
        int v0  = kt * 64;
        const __nv_bfloat16* srcs[4] = {
            g_hh[cur] + (size_t)m0 * NV + v0,
            g_hl[cur] + (size_t)m0 * NV + v0,
            g_gh      + (size_t)w0 * NV + v0,
            g_gl      + (size_t)w0 * NV + v0 };
        const uint32_t dsts[4] = {
            sbase + OFF_AH(buf), sbase + OFF_AL(buf),
            sbase + OFF_BH(buf), sbase + OFF_BL(buf) };
        #pragma unroll
        for (int i = 0; i < 8; i++) {
            const int mat = i >> 1;
            int cc = (i & 1) * 256 + tid;       // 0..511
            int row = cc >> 3, kc = cc & 7;
            cp_async16(dsts[mat] + row * 144 + kc * 16,
                       srcs[mat] + row * NV + kc * 8);
        }
        cp_commit();
    };

    fill(0);

    // ---- x_g[w] = sum_v g_xh[b][v] * ind_graph[w0+w][v] (overlaps tile-0 load)
    {
        int w = tid & 63, q = tid >> 6;
        const float4* ig = (const float4*)&ind_graph[(w0 + w) * NV + q * 256];
        const float4* xh = (const float4*)&g_xh[b][q * 256];
        float s = 0.f;
        #pragma unroll 16
        for (int j = 0; j < 64; j++) {
            float4 a = ig[j], c = xh[j];
            s += a.x * c.x + a.y * c.y + a.z * c.z + a.w * c.w;
        }
        part[q * 64 + w] = s;
    }
    __syncthreads();
    if (tid < 64)
        xg[tid] = part[tid] + part[64 + tid] + part[128 + tid] + part[192 + tid];

    // ---- GEMM: warp (wm = wid&3 -> m-tile, wn = wid>>2 -> 2 n-tiles) ----
    wmma::fragment<wmma::accumulator, 16, 16, 16, float> acc[2];
    wmma::fill_fragment(acc[0], 0.f);
    wmma::fill_fragment(acc[1], 0.f);
    const int wm = wid & 3, wn = wid >> 2;

    for (int kt = 0; kt < 16; kt++) {
        if (kt < 15) { fill(kt + 1); cp_wait1(); } else { cp_wait0(); }
        __syncthreads();                         // buffer kt ready
        const int buf = kt & 1;
        const __nv_bfloat16* Ah = (const __nv_bfloat16*)(smem + OFF_AH(buf));
        const __nv_bfloat16* Al = (const __nv_bfloat16*)(smem + OFF_AL(buf));
        const __nv_bfloat16* Bh = (const __nv_bfloat16*)(smem + OFF_BH(buf));
        const __nv_bfloat16* Bl = (const __nv_bfloat16*)(smem + OFF_BL(buf));
        #pragma unroll
        for (int ks = 0; ks < 4; ks++) {
            wmma::fragment<wmma::matrix_a, 16, 16, 16, __nv_bfloat16, wmma::row_major> fah, fal;
            wmma::load_matrix_sync(fah, Ah + wm * 16 * 72 + ks * 16, 72);
            wmma::load_matrix_sync(fal, Al + wm * 16 * 72 + ks * 16, 72);
            #pragma unroll
            for (int ni = 0; ni < 2; ni++) {
                wmma::fragment<wmma::matrix_b, 16, 16, 16, __nv_bfloat16, wmma::col_major> fbh, fbl;
                int boff = (wn * 2 + ni) * 16 * 72 + ks * 16;
                wmma::load_matrix_sync(fbh, Bh + boff, 72);
                wmma::load_matrix_sync(fbl, Bl + boff, 72);
                wmma::mma_sync(acc[ni], fah, fbh, acc[ni]);
                wmma::mma_sync(acc[ni], fah, fbl, acc[ni]);
                wmma::mma_sync(acc[ni], fal, fbh, acc[ni]);
            }
        }
        __syncthreads();                         // all reads done before refill
    }

    // ---- store h_diff (f32) into smem [64][72] (aliases dead buffers) ----
    wmma::store_matrix_sync(hd + wm * 16 * 72 + (wn * 2 + 0) * 16, acc[0], 72, wmma::mem_row_major);
    wmma::store_matrix_sync(hd + wm * 16 * 72 + (wn * 2 + 1) * 16, acc[1], 72, wmma::mem_row_major);
    __syncthreads();

    // ---- split h_diff -> bf16 hi/lo for the gate GEMM ----
    #pragma unroll
    for (int i = 0; i < 16; i++) {
        int idx = tid + i * 256;               // 4096
        int row = idx >> 6, col = idx & 63;
        float v = hd[row * 72 + col];
        __nv_bfloat16 hi = __float2bfloat16(v);
        hdh[row * 72 + col] = hi;
        hdl[row * 72 + col] = __float2bfloat16(v - __bfloat162float(hi));
    }
    __syncthreads();

    // ---- gates GEMM: gd[192 x 64] = W_hh · h_diff ----
    {
        const int gm = wid >> 1, gn = wid & 1;   // 3 m-tiles, 2 n-tiles per warp
        wmma::fragment<wmma::accumulator, 16, 16, 16, float> gacc[3][2];
        #pragma unroll
        for (int mi = 0; mi < 3; mi++)
            #pragma unroll
            for (int ni = 0; ni < 2; ni++) wmma::fill_fragment(gacc[mi][ni], 0.f);
        #pragma unroll
        for (int ks = 0; ks < 4; ks++) {
            wmma::fragment<wmma::matrix_b, 16, 16, 16, __nv_bfloat16, wmma::row_major> gbh[2], gbl[2];
            #pragma unroll
            for (int ni = 0; ni < 2; ni++) {
                int boff = ks * 16 * 72 + (gn * 2 + ni) * 16;
                wmma::load_matrix_sync(gbh[ni], hdh + boff, 72);
                wmma::load_matrix_sync(gbl[ni], hdl + boff, 72);
            }
            #pragma unroll
            for (int mi = 0; mi < 3; mi++) {
                wmma::fragment<wmma::matrix_a, 16, 16, 16, __nv_bfloat16, wmma::row_major> fah, fal;
                int aoff = (gm * 3 + mi) * 16 * 64 + ks * 16;
                wmma::load_matrix_sync(fah, g_whh_h + aoff, 64);
                wmma::load_matrix_sync(fal, g_whh_l + aoff, 64);
                #pragma unroll
                for (int ni = 0; ni < 2; ni++) {
                    wmma::mma_sync(gacc[mi][ni], fah, gbh[ni], gacc[mi][ni]);
                    wmma::mma_sync(gacc[mi][ni], fah, gbl[ni], gacc[mi][ni]);
                    wmma::mma_sync(gacc[mi][ni], fal, gbh[ni], gacc[mi][ni]);
                }
            }
        }
        #pragma unroll
        for (int mi = 0; mi < 3; mi++)
            #pragma unroll
            for (int ni = 0; ni < 2; ni++)
                wmma::store_matrix_sync(gd + (gm * 3 + mi) * 16 * 72 + (gn * 2 + ni) * 16,
                                        gacc[mi][ni], 72, wmma::mem_row_major);
    }
    __syncthreads();

    // ---- nonlinearity + state update: thread = (hh, wq), 16 nodes ----
    {
        const int hh = tid >> 2;
        const int wq = tid & 3;
        float wih_r = W_ih[hh],  wih_z = W_ih[64 + hh],  wih_n = W_ih[128 + hh];
        float bi_r  = b_ih[hh] + b_hh[hh];
        float bi_z  = b_ih[64 + hh] + b_hh[64 + hh];
        float bi_n  = b_ih[128 + hh];
        float bh_n  = b_hh[128 + hh];
        #pragma unroll
        for (int k = 0; k < 16; k++) {
            int w = wq + 4 * k;
            float ar = gd[hh * 72 + w];
            float az = gd[(64 + hh) * 72 + w];
            float an = gd[(128 + hh) * 72 + w];
            float xgv = xg[w];
            float r = 1.f / (1.f + __expf(-(ar + wih_r * xgv + bi_r)));
            float z = 1.f / (1.f + __expf(-(az + wih_z * xgv + bi_z)));
            float n = tanhf(wih_n * xgv + bi_n + r * (an + bh_n));
            float hd_self = hd[hh * 72 + w];
            float hnew = (1.f - z) * n + z * hd_self;
            size_t si = (size_t)(m0 + hh) * NV + w0 + w;
            __nv_bfloat16 hi = __float2bfloat16(hnew);
            g_hh[nxt][si] = hi;
            g_hl[nxt][si] = __float2bfloat16(hnew - __bfloat162float(hi));
            stcs(&out_reprs[((b * HID + hh) * NV + (w0 + w)) * NT + t], hnew);
            hn[hh * 72 + w] = hnew;
        }
    }
    __syncthreads();

    // ---- fused epilogue: imps(t), preds(t+1), g_xh(t+1) ----
    {
        int w = tid & 63, q = tid >> 6;
        float so = 0.f, si = 0.f;
        #pragma unroll
        for (int j = 0; j < 16; j++) {
            int hh = q * 16 + j;
            float hv = hn[hh * 72 + w];
            so += W_out[hh]  * hv;
            si += W_init[hh] * hv;
        }
        part[q * 64 + w]       = so;
        part[256 + q * 64 + w] = si;
    }
    __syncthreads();
    if (tid < 64) {
        int w = tid;
        float so = part[w] + part[64 + w] + part[128 + w] + part[192 + w];
        stcs(&out_imps[(b * NV + w0 + w) * NT + t], so + b_out[0]);
        if (t < NT - 1) {
            float si = part[256 + w] + part[320 + w] + part[384 + w] + part[448 + w];
            float d = si + b_init[0];
            int xi = (b * NV + w0 + w) * NT + (t + 1);
            int mode = g_mask_mode;
            bool m;
            if (mode == 0)      m = mask_raw[xi] != 0;
            else if (mode == 1) m = ((const int*)mask_raw)[xi] != 0;
            else                m = ((const float*)mask_raw)[xi] != 0.f;
            g_xh[b][w0 + w] = m ? x[xi] : d;
            stcs(&out_preds[xi], d);
        }
    }
}

// ---------------------------------------------------------------------------
extern "C" void kernel_launch(void* const* d_in, const int* in_sizes, int n_in,
                              void* d_out, int out_size) {
    const float* x          = (const float*)d_in[0];
    const unsigned char* mk = (const unsigned char*)d_in[1];
    const float* graph      = (const float*)d_in[2];
    const float* ind_graph  = (const float*)d_in[3];
    const float* h0         = (const float*)d_in[4];
    const float* W_init     = (const float*)d_in[5];
    const float* b_init     = (const float*)d_in[6];
    const float* W_out      = (const float*)d_in[7];
    const float* b_out      = (const float*)d_in[8];
    const float* W_ih       = (const float*)d_in[9];
    const float* W_hh       = (const float*)d_in[10];
    const float* b_ih       = (const float*)d_in[11];
    const float* b_hh       = (const float*)d_in[12];

    float* out_imps  = (float*)d_out;
    float* out_preds = out_imps + BSZ * NV * NT;
    float* out_reprs = out_preds + BSZ * NV * NT;

    cudaFuncSetAttribute(step_tc_kernel, cudaFuncAttributeMaxDynamicSharedMemorySize,
                         SMEM_TOTAL);

    detect_mask_kernel<<<1, 256>>>((const unsigned int*)mk);
    split_graph_kernel<<<NV * NV / 256, 256>>>(graph);
    split_whh_kernel<<<192 * 64 / 256, 256>>>(W_hh);
    init_h_kernel<<<BSZ * HID * NV / 256, 256>>>(h0);
    prep_kernel<<<dim3(4, BSZ), 256>>>(x, mk, h0, W_init, b_init, out_preds);
    for (int t = 0; t < NT; t++) {
        step_tc_kernel<<<dim3(16, BSZ), 256, SMEM_TOTAL>>>(
            t, t & 1, x, mk, ind_graph,
            W_init, b_init, W_out, b_out, W_ih, b_ih, b_hh,
            out_imps, out_preds, out_reprs);
    }
}